// round 10
// baseline (speedup 1.0000x reference)
#include <cuda_runtime.h>
#include <math_constants.h>

// Problem constants (fixed by setup_inputs)
#define BS     32
#define C      128
#define GN     256
#define S      16
#define NTILES 4096          // G / NG
#define NG     2             // groups per tile (consecutive gn -> memory adjacent)
#define NBLK   740           // 5 blocks per SM on 148 SMs, persistent, one wave
#define NT     256
#define MAXN   9             // bg + up to 8 fg instances (labels in [-1,8))
#define INVT   5.0f          // 1 / T, T = 0.2
#define WLOSS  0.1f

__device__ float2   g_part[NBLK];   // per-block (sum gl*gv, sum gv)
__device__ unsigned g_ctr = 0;      // completed-block counter (self-resetting)

__global__ __launch_bounds__(NT, 5)
void fused_kernel(const int*   __restrict__ lab_g,   // [bs, Gn, S]
                  const float* __restrict__ feat_g,  // [bs, C, Gn, S]
                  const int*   __restrict__ idx_g,   // [bs, Gn, S]
                  const float* __restrict__ ctx,     // [1, C]
                  float*       __restrict__ out)
{
    __shared__ __align__(16) float4 st4[2][C][8];       // double-buffered tile, 32KB
    __shared__ __align__(16) float  Mrow[NG][MAXN][C];  // instance means, 9KB
    __shared__ __align__(16) float  W[NG][MAXN][S];     // per-slot weights, 1.125KB
    __shared__ int    instNumB[2][NG];                  // double-buffered (phase3 vs next phase1)
    __shared__ int    hasBg[NG];
    __shared__ int    sIsLast;
    __shared__ float  red[16];

    const int t    = threadIdx.x;
    const int lane = t & 31;
    const unsigned sb0 = (unsigned)__cvta_generic_to_shared(&st4[0][0][0]);
    const int   c2   = t & 127;                 // phase-2 channel
    const int   gl2  = t >> 7;                  // phase-2 local group
    const float ctxv = __ldg(ctx + c2);

    int   tile = blockIdx.x;
    int   buf  = 0;
    float ax = 0.0f, ay = 0.0f;                 // per-warp loss accumulators
    int   pIdx = 0, pLab = 0;                   // prefetched metadata (warps 0,1)

    // ---------------- prologue: stage first tile + its metadata ----------------
    if (tile < NTILES) {
        const int g0 = tile * NG, b = g0 / GN, gn0 = g0 % GN;
        const float4* src = (const float4*)(feat_g + ((size_t)b * C * GN + gn0) * S);
        #pragma unroll
        for (int q = 0; q < 4; ++q) {
            int f4 = t + q * NT;                // 0..1023
            int c  = f4 >> 3, k = f4 & 7;
            unsigned dst = sb0 + (unsigned)((c * 8 + (k ^ (c & 7))) * 16);
            const void* gp = (const void*)(src + (size_t)c * (GN * S / 4) + k);
            asm volatile("cp.async.cg.shared.global [%0], [%1], 16;" :: "r"(dst), "l"(gp));
        }
        asm volatile("cp.async.commit_group;");
        if (t < 64 && lane < S) {
            int grp = g0 + (t >> 5);
            pIdx = idx_g[(size_t)grp * S + lane];
            pLab = lab_g[(size_t)grp * S + lane];
        }
    }

    // ---------------- persistent tile loop (double-buffered) ----------------
    for (; tile < NTILES; tile += NBLK) {
        const int  nextTile = tile + NBLK;
        const bool hasNext  = nextTile < NTILES;

        // issue prefetch of next tile into the other buffer
        if (hasNext) {
            const int g0n = nextTile * NG, bn = g0n / GN, gn0n = g0n % GN;
            const float4* src = (const float4*)(feat_g + ((size_t)bn * C * GN + gn0n) * S);
            const unsigned sb = sb0 + (unsigned)((buf ^ 1) * (C * 8 * 16));
            #pragma unroll
            for (int q = 0; q < 4; ++q) {
                int f4 = t + q * NT;
                int c  = f4 >> 3, k = f4 & 7;
                unsigned dst = sb + (unsigned)((c * 8 + (k ^ (c & 7))) * 16);
                const void* gp = (const void*)(src + (size_t)c * (GN * S / 4) + k);
                asm volatile("cp.async.cg.shared.global [%0], [%1], 16;" :: "r"(dst), "l"(gp));
            }
            asm volatile("cp.async.commit_group;");
        }

        // phase 1: warp-parallel slot metadata -> weight matrix W (warps 0,1)
        if (t < 64) {
            const int  w  = t >> 5;
            const bool sm = lane < S;
            int myIdx = sm ? pIdx : (0x40000000 | lane);   // unique sentinels on lanes >= S
            int myLab = sm ? pLab : 0;
            unsigned mi    = __match_any_sync(0xffffffffu, myIdx);
            bool     leadI = sm && (lane == (__ffs(mi) - 1));
            int      u     = __popc(__ballot_sync(0xffffffffu, leadI));  // distinct seed idx count
            bool     valid = sm && (lane < u);
            int      labm  = valid ? myLab : (0x41000000 | lane);
            unsigned ml    = __match_any_sync(0xffffffffu, labm);
            bool     isBg  = valid && (myLab < 0);
            bool     isFg  = valid && (myLab >= 0);
            int      leadLane = __ffs(ml) - 1;
            unsigned fgLead   = __ballot_sync(0xffffffffu, isFg && (lane == leadLane));
            unsigned bgB      = __ballot_sync(0xffffffffu, isBg);
            int      nfg      = __popc(fgLead);
            int   slot  = -1;
            float scale = 0.0f;
            if (valid) {
                scale = 1.0f / (float)__popc(ml);
                slot  = isBg ? 0 : (1 + __popc(fgLead & ((1u << leadLane) - 1u)));
            }
            if (sm) {
                #pragma unroll
                for (int k = 0; k < MAXN; ++k)
                    W[w][k][lane] = (slot == k) ? scale : 0.0f;   // one-hot weighted column
            }
            if (lane == 0) { instNumB[buf][w] = nfg + 1; hasBg[w] = (bgB != 0); }
            // prefetch next tile's metadata (lands during phases 2-3)
            if (hasNext && sm) {
                int grpN = nextTile * NG + w;
                pIdx = idx_g[(size_t)grpN * S + lane];
                pLab = lab_g[(size_t)grpN * S + lane];
            }
        }
        if (hasNext) asm volatile("cp.async.wait_group 1;");   // current tile resident
        else         asm volatile("cp.async.wait_group 0;");
        __syncthreads();                                       // B1

        // phase 2: per-instance means = dense 9x16 contraction (no predicates)
        {
            float acc[MAXN];
            #pragma unroll
            for (int k = 0; k < MAXN; ++k) acc[k] = 0.0f;
            const float4 (*stb)[8] = st4[buf];
            const float4* Wv = (const float4*)&W[gl2][0][0];   // W[k] = 4 float4
            #pragma unroll
            for (int q = 0; q < 4; ++q) {
                float4 fv = stb[c2][(gl2 * 4 + q) ^ (c2 & 7)];
                #pragma unroll
                for (int k = 0; k < MAXN; ++k) {
                    float4 wq = Wv[k * 4 + q];                 // broadcast LDS.128
                    acc[k] += fv.x * wq.x + fv.y * wq.y + fv.z * wq.z + fv.w * wq.w;
                }
            }
            #pragma unroll
            for (int k = 0; k < MAXN; ++k) Mrow[gl2][k][c2] = acc[k];
            if (!hasBg[gl2]) Mrow[gl2][0][c2] = ctxv;
        }
        __syncthreads();                                       // B2

        // phase 3: sim rows + logsumexp, half-warp per row (warp = 2 rows)
        {
            const int w   = t >> 5;        // 0..7
            const int glw = w >> 2;
            const int r   = w & 3;
            const int hl  = lane >> 4;     // half index -> row select
            const int cl  = lane & 15;     // 8 channels per lane
            const int n   = instNumB[buf][glw];
            const int row = 1 + r + 4 * hl;        // 1..8
            const int fg  = n - 1;
            const float4* Mv = (const float4*)&Mrow[glw][0][0];   // 32 float4 per row
            float4 a0 = Mv[row * 32 + cl * 2];
            float4 a1 = Mv[row * 32 + cl * 2 + 1];
            float p[MAXN];
            #pragma unroll
            for (int j = 0; j < MAXN; ++j) {
                float4 b0 = Mv[j * 32 + cl * 2];
                float4 b1 = Mv[j * 32 + cl * 2 + 1];
                p[j] = a0.x*b0.x + a0.y*b0.y + a0.z*b0.z + a0.w*b0.w
                     + a1.x*b1.x + a1.y*b1.y + a1.z*b1.z + a1.w*b1.w;
            }
            #pragma unroll
            for (int o = 8; o > 0; o >>= 1) {      // 4-stage butterfly within 16-lane half
                #pragma unroll
                for (int j = 0; j < MAXN; ++j)
                    p[j] += __shfl_xor_sync(0xffffffffu, p[j], o);
            }
            float m = -CUDART_INF_F;
            #pragma unroll
            for (int j = 0; j < MAXN; ++j) {
                p[j] = (j < n) ? p[j] * INVT : -CUDART_INF_F;
                m = fmaxf(m, p[j]);
            }
            float ssum = 0.f, diag = 0.f;
            #pragma unroll
            for (int j = 0; j < MAXN; ++j) {
                ssum += __expf(p[j] - m);
                if (j == row) diag = p[j];
            }
            float li = (row < n) ? (m + __logf(ssum) - diag) : 0.0f;
            li += __shfl_xor_sync(0xffffffffu, li, 16);        // combine the 2 rows
            if (fg >= 1) {
                ax += li / (float)fg;                          // partial: 4 warps cover rows 1-8
                if (r == 0) ay += 1.0f;                        // group validity counted once
            }
        }
        buf ^= 1;
    }

    // ---------------- epilogue: combine 8 warp accumulators, one atomic per block ----------------
    __syncthreads();
    if (lane == 0) { red[t >> 5] = ax; red[8 + (t >> 5)] = ay; }
    __syncthreads();
    if (t == 0) {
        float sx = 0.f, sy = 0.f;
        #pragma unroll
        for (int q = 0; q < 8; ++q) { sx += red[q]; sy += red[8 + q]; }
        g_part[blockIdx.x] = make_float2(sx, sy);
        __threadfence();                          // publish before signaling
        unsigned o = atomicAdd(&g_ctr, 1u);
        sIsLast = (o == (unsigned)(NBLK - 1));
    }
    __syncthreads();

    if (sIsLast) {
        if (t == 0) __threadfence();              // acquire all g_part writes
        __syncthreads();
        float sx = 0.f, sy = 0.f;
        for (int i = t; i < NBLK; i += NT) {
            float2 v = g_part[i];
            sx += v.x; sy += v.y;
        }
        #pragma unroll
        for (int o = 16; o > 0; o >>= 1) {
            sx += __shfl_xor_sync(0xffffffffu, sx, o);
            sy += __shfl_xor_sync(0xffffffffu, sy, o);
        }
        if (lane == 0) { red[t >> 5] = sx; red[8 + (t >> 5)] = sy; }
        __syncthreads();
        if (t == 0) {
            float fx = 0.f, fy = 0.f;
            #pragma unroll
            for (int q = 0; q < 8; ++q) { fx += red[q]; fy += red[8 + q]; }
            out[0] = fx / fy * WLOSS;
            atomicExch(&g_ctr, 0u);               // visible reset for next graph replay
        }
    }
}

extern "C" void kernel_launch(void* const* d_in, const int* in_sizes, int n_in,
                              void* d_out, int out_size)
{
    const int*   lab  = (const int*)  d_in[0];   // proposal_instance_mask
    const float* feat = (const float*)d_in[1];   // grouped_features
    const int*   idx  = (const int*)  d_in[2];   // grouped_indices
    const float* ctx  = (const float*)d_in[3];   // context_compen
    (void)in_sizes; (void)n_in; (void)out_size;

    fused_kernel<<<NBLK, NT>>>(lab, feat, idx, ctx, (float*)d_out);
}